// round 11
// baseline (speedup 1.0000x reference)
#include <cuda_runtime.h>
#include <cuda_fp16.h>
#include <cstdint>

#define NBATCH 4096
#define NTOK   64
#define NDIM   256
#define NHEADS 8
#define HD     32
#define NROWS  (NBATCH * NTOK)   // 262144

// ---------------- device scratch ---------------------------------------------
__device__ __align__(16) __half g_xf[(size_t)NROWS * 256];
__device__ __align__(16) __half g_wqf[768 * 256];   // [col][k]
__device__ __align__(16) __half g_wpf[256 * 256];   // [col][k]
__device__ float g_bias[NHEADS * NTOK * NTOK];      // [h][n][m]

// ---------------- smem layout (bytes) ----------------------------------------
// W ring: 3 x 16896 (32 cols x 528B rows)  | per-row pad 16B for LDSM banks
#define WBUF_STRIDE 16896
#define WB_OFF 0
#define QH_OFF 50688
#define QL_OFF 84480
#define KS_OFF 118272
#define VS_OFF 152064
#define UN_OFF 185856              // phase B: X tile [64][264]; phase C: S buffers
#define SMEM_TOT 222720

// ---------------- helpers ----------------------------------------------------
__device__ __forceinline__ uint32_t s2u(const void* p) {
    return (uint32_t)__cvta_generic_to_shared(p);
}
__device__ __forceinline__ void hsplit2(float a, float b, uint32_t& hi, uint32_t& lo) {
    __half ha = __float2half_rn(a), hb = __float2half_rn(b);
    __half la = __float2half_rn(a - __half2float(ha));
    __half lb = __float2half_rn(b - __half2float(hb));
    __half2 H = __halves2half2(ha, hb);
    __half2 L = __halves2half2(la, lb);
    hi = *(uint32_t*)&H; lo = *(uint32_t*)&L;
}
#define LDM4(r0, r1, r2, r3, addr)                                              \
    asm volatile("ldmatrix.sync.aligned.m8n8.x4.shared.b16 {%0,%1,%2,%3}, [%4];"\
                 : "=r"(r0), "=r"(r1), "=r"(r2), "=r"(r3) : "r"(addr))
#define LDM4T(r0, r1, r2, r3, addr)                                             \
    asm volatile("ldmatrix.sync.aligned.m8n8.x4.trans.shared.b16 {%0,%1,%2,%3}, [%4];"\
                 : "=r"(r0), "=r"(r1), "=r"(r2), "=r"(r3) : "r"(addr))
#define CP16(dst, src)                                                          \
    asm volatile("cp.async.cg.shared.global [%0], [%1], 16;" :: "r"(dst), "l"(src))
#define CP_COMMIT() asm volatile("cp.async.commit_group;")
#define CP_WAIT0()  asm volatile("cp.async.wait_group 0;")
#define CP_WAIT1()  asm volatile("cp.async.wait_group 1;")

__device__ __forceinline__ void mma16h(float* c, const uint32_t* a, const uint32_t* b) {
    asm volatile(
        "mma.sync.aligned.m16n8k16.row.col.f32.f16.f16.f32 "
        "{%0,%1,%2,%3}, {%4,%5,%6,%7}, {%8,%9}, {%0,%1,%2,%3};"
        : "+f"(c[0]), "+f"(c[1]), "+f"(c[2]), "+f"(c[3])
        : "r"(a[0]), "r"(a[1]), "r"(a[2]), "r"(a[3]), "r"(b[0]), "r"(b[1]));
}

// ---------------------------------------------------------------------------
// Prep: x -> fp16, weights -> fp16 [col][k], bias matrix.
// ---------------------------------------------------------------------------
__global__ void prep_all(const float* __restrict__ x,
                         const float* __restrict__ wq, const float* __restrict__ wkv,
                         const float* __restrict__ pw,
                         const float* __restrict__ bias_table,
                         const int* __restrict__ rel_idx)
{
    const int bid = blockIdx.x;
    if (bid < 65536) {
        size_t i = (size_t)bid * 256 + threadIdx.x;
        float4 v = ((const float4*)x)[i];
        __half2 a = __floats2half2_rn(v.x, v.y);
        __half2 b = __floats2half2_rn(v.z, v.w);
        ((uint2*)g_xf)[i] = make_uint2(*(uint32_t*)&a, *(uint32_t*)&b);
    } else if (bid < 66304) {
        int idx = (bid - 65536) * 256 + threadIdx.x;
        int c = idx >> 8, k = idx & 255;
        float v = (c < 256) ? wq[k * 256 + c] : wkv[k * 512 + (c - 256)];
        g_wqf[idx] = __float2half_rn(v);
    } else if (bid < 66560) {
        int idx = (bid - 66304) * 256 + threadIdx.x;
        int c = idx >> 8, k = idx & 255;
        g_wpf[idx] = __float2half_rn(pw[k * 256 + c]);
    } else {
        int idx = (bid - 66560) * 256 + threadIdx.x;
        int h = idx >> 12, rm = idx & 4095;
        g_bias[idx] = bias_table[rel_idx[rm] * NHEADS + h];
    }
}

// ---------------------------------------------------------------------------
// Fused per-window kernel: qkv GEMM -> 8-head attention -> proj GEMM.
// Block = 1 window, 256 threads / 8 warps. All intermediates in smem.
// ---------------------------------------------------------------------------
__global__ __launch_bounds__(256, 1) void fused_win(
    const float* __restrict__ bq, const float* __restrict__ bkv,
    const float* __restrict__ pb, const float* __restrict__ w,
    float* __restrict__ outp)
{
    extern __shared__ __align__(16) char sm[];
    const uint32_t sb = s2u(sm);
    const int win = blockIdx.x;
    const int t = threadIdx.x, lane = t & 31, wid = t >> 5;
    const int gid = lane >> 2, t4 = lane & 3;
    const int wm = wid & 3, wn = wid >> 2;   // GEMM warp grid 4m x 2n (tile 16x16)

    const int arow = (lane & 7) + ((lane >> 3) & 1) * 8;
    const int aksh = ((lane >> 4) & 1) * 8;
    const int brow = (lane & 7) + ((lane >> 4) & 1) * 8;
    const int bksh = ((lane >> 3) & 1) * 8;
    const int vrow = arow;
    const int vcsh = ((lane >> 4) & 1) * 8;

    // ---- prologue: X tile + first W chunk ----
    {
        const __half* xsrc = g_xf + (size_t)win * (64 * 256);
#pragma unroll
        for (int j = 0; j < 8; j++) {
            const int idx = j * 256 + t;
            const int r = idx >> 5, q = idx & 31;
            CP16(sb + UN_OFF + r * 528 + q * 16, xsrc + r * 256 + q * 8);
        }
        CP_COMMIT();
    }
#define LOADW(SRC, C, BUF)                                                       \
    do {                                                                         \
        _Pragma("unroll")                                                        \
        for (int j = 0; j < 4; j++) {                                            \
            const int idx = j * 256 + t;                                         \
            const int col = idx >> 5, q = idx & 31;                              \
            CP16(sb + WB_OFF + (uint32_t)(BUF) * WBUF_STRIDE + col * 528 + q * 16,\
                 (SRC) + (size_t)((C) * 32 + col) * 256 + q * 8);                \
        }                                                                        \
        CP_COMMIT();                                                             \
    } while (0)

    LOADW(g_wqf, 0, 0);

    const float scl = 0.17677669529663687f;   // 32^-0.5

    // ======== Phase B: qkv GEMM, 24 chunks of 32 cols ========
    for (int c = 0; c < 24; c++) {
        if (c < 23) { LOADW(g_wqf, c + 1, (c + 1) % 3); CP_WAIT1(); }
        else        { CP_WAIT0(); }
        __syncthreads();
        const uint32_t bbase = WB_OFF + (uint32_t)(c % 3) * WBUF_STRIDE;

        float acc[2][4];
#pragma unroll
        for (int nt = 0; nt < 2; nt++)
#pragma unroll
            for (int i = 0; i < 4; i++) acc[nt][i] = 0.f;

#pragma unroll
        for (int kk = 0; kk < 16; kk++) {
            uint32_t a[4], b[4];
            LDM4(a[0], a[1], a[2], a[3],
                 sb + UN_OFF + (wm * 16 + arow) * 528 + (kk * 16 + aksh) * 2);
            LDM4(b[0], b[1], b[2], b[3],
                 sb + bbase + (wn * 16 + brow) * 528 + (kk * 16 + bksh) * 2);
            mma16h(acc[0], a, b);
            mma16h(acc[1], a, b + 2);
        }

        // epilogue: scatter into QH/QL (scaled) / KS / VS
        const int region = (c * 32) >> 8;          // chunk fully inside a region
#pragma unroll
        for (int nt = 0; nt < 2; nt++) {
            const int gc = c * 32 + wn * 16 + nt * 8 + t4 * 2;
            const int c2 = gc & 255;
#pragma unroll
            for (int h8 = 0; h8 < 2; h8++) {
                const int row = wm * 16 + gid + h8 * 8;
                const float v0 = acc[nt][h8 * 2 + 0];
                const float v1 = acc[nt][h8 * 2 + 1];
                if (region == 0) {
                    const float2 bv = *(const float2*)(bq + c2);
                    uint32_t hi, lo;
                    hsplit2((v0 + bv.x) * scl, (v1 + bv.y) * scl, hi, lo);
                    *(uint32_t*)(sm + QH_OFF + row * 528 + c2 * 2) = hi;
                    *(uint32_t*)(sm + QL_OFF + row * 528 + c2 * 2) = lo;
                } else {
                    const float2 bv =
                        *(const float2*)(bkv + (region == 1 ? c2 : 256 + c2));
                    __half2 p = __floats2half2_rn(v0 + bv.x, v1 + bv.y);
                    *(uint32_t*)(sm + (region == 1 ? KS_OFF : VS_OFF)
                                 + row * 528 + c2 * 2) = *(uint32_t*)&p;
                }
            }
        }
    }
    __syncthreads();      // q/k/v complete; X region now dead (becomes S)

    LOADW(g_wpf, 0, 0);   // prefetch proj chunk 0 (overlaps attention)

    // mixing weights ww = softmax(w)
    const float w0 = w[0], w1 = w[1];
    const float wmx = fmaxf(w0, w1);
    const float e0 = __expf(w0 - wmx), e1 = __expf(w1 - wmx);
    const float winv = 1.f / (e0 + e1);
    const float ww0 = e0 * winv, ww1 = e1 * winv;

    // ======== Phase C: attention, 4 head pairs (warp-local, no block sync) ====
    const int w4 = wid & 3;            // row-group within head
    const int hgrp = wid >> 2;         // 0/1 -> even/odd head of the pair
    const int r0 = w4 * 16 + gid;
    const uint32_t sh0 = UN_OFF + wid * 4608;
    const uint32_t sl0 = sh0 + 2304;

    for (int hp = 0; hp < 4; hp++) {
        const int h = hp * 2 + hgrp;
        const int hc = h * 32;

        // ---- S = Q@K^T (2-term: qh,ql vs k) ----
        float s8[8][4];
#pragma unroll
        for (int nt = 0; nt < 8; nt++)
#pragma unroll
            for (int i = 0; i < 4; i++) s8[nt][i] = 0.f;

#pragma unroll
        for (int kk = 0; kk < 2; kk++) {
            const int kb16 = kk * 16;
            uint32_t ah[4], al[4];
            const uint32_t qoff =
                (uint32_t)((w4 * 16 + arow) * 528 + (hc + kb16 + aksh) * 2);
            LDM4(ah[0], ah[1], ah[2], ah[3], sb + QH_OFF + qoff);
            LDM4(al[0], al[1], al[2], al[3], sb + QL_OFF + qoff);
#pragma unroll
            for (int ntp = 0; ntp < 4; ntp++) {
                uint32_t bk[4];
                LDM4(bk[0], bk[1], bk[2], bk[3],
                     sb + KS_OFF + (ntp * 16 + brow) * 528 + (hc + kb16 + bksh) * 2);
                mma16h(s8[2 * ntp],     ah, bk);
                mma16h(s8[2 * ntp],     al, bk);
                mma16h(s8[2 * ntp + 1], ah, bk + 2);
                mma16h(s8[2 * ntp + 1], al, bk + 2);
            }
        }

        // ---- bias add ----
        const float* b0p = g_bias + ((size_t)h * 64 + r0) * 64;
        const float* b1p = b0p + 8 * 64;
#pragma unroll
        for (int nt = 0; nt < 8; nt++) {
            const int cc = nt * 8 + 2 * t4;
            const float2 x0 = *(const float2*)(b0p + cc);
            const float2 x1 = *(const float2*)(b1p + cc);
            s8[nt][0] += x0.x; s8[nt][1] += x0.y;
            s8[nt][2] += x1.x; s8[nt][3] += x1.y;
        }

        // ---- softmax sums (4-lane shfl) ----
        float p0 = 0.f, p1 = 0.f;
#pragma unroll
        for (int nt = 0; nt < 8; nt++) {
            p0 += __expf(s8[nt][0]) + __expf(s8[nt][1]);
            p1 += __expf(s8[nt][2]) + __expf(s8[nt][3]);
        }
        p0 += __shfl_xor_sync(0xFFFFFFFF, p0, 1);
        p0 += __shfl_xor_sync(0xFFFFFFFF, p0, 2);
        p1 += __shfl_xor_sync(0xFFFFFFFF, p1, 1);
        p1 += __shfl_xor_sync(0xFFFFFFFF, p1, 2);
        const float k00 = ww0 / p0, k01 = ww0 / p1;

        // ---- combined weights -> S hi/lo fp16 smem ----
#pragma unroll
        for (int nt = 0; nt < 8; nt++) {
            const int cc = nt * 8 + 2 * t4;
            const float q00 = fmaxf(s8[nt][0], 0.f), q01 = fmaxf(s8[nt][1], 0.f);
            const float q10 = fmaxf(s8[nt][2], 0.f), q11 = fmaxf(s8[nt][3], 0.f);
            const float a0 = __expf(s8[nt][0]) * k00 + q00 * q00 * ww1;
            const float a1 = __expf(s8[nt][1]) * k00 + q01 * q01 * ww1;
            const float a2 = __expf(s8[nt][2]) * k01 + q10 * q10 * ww1;
            const float a3 = __expf(s8[nt][3]) * k01 + q11 * q11 * ww1;
            uint32_t hi, lo;
            hsplit2(a0, a1, hi, lo);
            *(uint32_t*)(sm + sh0 + gid * 144 + cc * 2) = hi;
            *(uint32_t*)(sm + sl0 + gid * 144 + cc * 2) = lo;
            hsplit2(a2, a3, hi, lo);
            *(uint32_t*)(sm + sh0 + (gid + 8) * 144 + cc * 2) = hi;
            *(uint32_t*)(sm + sl0 + (gid + 8) * 144 + cc * 2) = lo;
        }
        __syncwarp();

        // ---- O = A @ V (2-term), V via ldmatrix.trans ----
        float o[4][4];
#pragma unroll
        for (int nt = 0; nt < 4; nt++)
#pragma unroll
            for (int i = 0; i < 4; i++) o[nt][i] = 0.f;

#pragma unroll
        for (int kc = 0; kc < 4; kc++) {
            const int kb16 = kc * 16;
            uint32_t ah[4], al[4];
            const uint32_t soff = (uint32_t)(arow * 144 + (kb16 + aksh) * 2);
            LDM4(ah[0], ah[1], ah[2], ah[3], sb + sh0 + soff);
            LDM4(al[0], al[1], al[2], al[3], sb + sl0 + soff);
#pragma unroll
            for (int ntp = 0; ntp < 2; ntp++) {
                uint32_t bv[4];
                LDM4T(bv[0], bv[1], bv[2], bv[3],
                      sb + VS_OFF + (kb16 + vrow) * 528
                      + (hc + ntp * 16 + vcsh) * 2);
                mma16h(o[2 * ntp],     ah, bv);
                mma16h(o[2 * ntp],     al, bv);
                mma16h(o[2 * ntp + 1], ah, bv + 2);
                mma16h(o[2 * ntp + 1], al, bv + 2);
            }
        }
        __syncwarp();

        // ---- write O fp16 into QH region (this head's columns; rows are ours)
#pragma unroll
        for (int nt = 0; nt < 4; nt++) {
            const int d = nt * 8 + 2 * t4;
            __half2 v0 = __floats2half2_rn(o[nt][0], o[nt][1]);
            __half2 v1 = __floats2half2_rn(o[nt][2], o[nt][3]);
            *(uint32_t*)(sm + QH_OFF + r0 * 528 + (hc + d) * 2) = *(uint32_t*)&v0;
            *(uint32_t*)(sm + QH_OFF + (r0 + 8) * 528 + (hc + d) * 2) = *(uint32_t*)&v1;
        }
    }

    // ======== Phase D: proj GEMM, 8 chunks of 32 cols (A = O in QH) ========
    for (int c = 0; c < 8; c++) {
        if (c < 7) { LOADW(g_wpf, c + 1, (c + 1) % 3); CP_WAIT1(); }
        else       { CP_WAIT0(); }
        __syncthreads();   // also orders attention O-writes before first compute
        const uint32_t bbase = WB_OFF + (uint32_t)(c % 3) * WBUF_STRIDE;

        float acc[2][4];
#pragma unroll
        for (int nt = 0; nt < 2; nt++)
#pragma unroll
            for (int i = 0; i < 4; i++) acc[nt][i] = 0.f;

#pragma unroll
        for (int kk = 0; kk < 16; kk++) {
            uint32_t a[4], b[4];
            LDM4(a[0], a[1], a[2], a[3],
                 sb + QH_OFF + (wm * 16 + arow) * 528 + (kk * 16 + aksh) * 2);
            LDM4(b[0], b[1], b[2], b[3],
                 sb + bbase + (wn * 16 + brow) * 528 + (kk * 16 + bksh) * 2);
            mma16h(acc[0], a, b);
            mma16h(acc[1], a, b + 2);
        }

#pragma unroll
        for (int nt = 0; nt < 2; nt++) {
            const int gc = c * 32 + wn * 16 + nt * 8 + t4 * 2;
            const float2 pbv = *(const float2*)(pb + gc);
#pragma unroll
            for (int h8 = 0; h8 < 2; h8++) {
                const size_t grow = (size_t)win * 64 + wm * 16 + gid + h8 * 8;
                float2 o2;
                o2.x = acc[nt][h8 * 2 + 0] + pbv.x;
                o2.y = acc[nt][h8 * 2 + 1] + pbv.y;
                *(float2*)(outp + grow * 256 + gc) = o2;
            }
        }
    }
#undef LOADW
}

// ---------------------------------------------------------------------------
extern "C" void kernel_launch(void* const* d_in, const int* in_sizes, int n_in,
                              void* d_out, int out_size)
{
    const float* x   = (const float*)d_in[0];
    const float* wq  = (const float*)d_in[1];
    const float* bq  = (const float*)d_in[2];
    const float* wkv = (const float*)d_in[3];
    const float* bkv = (const float*)d_in[4];
    const float* bt  = (const float*)d_in[5];
    const float* w   = (const float*)d_in[6];
    const float* pw  = (const float*)d_in[7];
    const float* pb  = (const float*)d_in[8];
    const int*   ri  = (const int*)d_in[9];
    float* out = (float*)d_out;

    // REQUIRED: dynamic smem > 48KB default (R9 lesson).
    cudaFuncSetAttribute(fused_win, cudaFuncAttributeMaxDynamicSharedMemorySize,
                         SMEM_TOT);

    prep_all<<<66688, 256>>>(x, wq, wkv, pw, bt, ri);
    fused_win<<<NBATCH, 256, SMEM_TOT>>>(bq, bkv, pb, w, out);
}

// round 12
// speedup vs baseline: 1.3825x; 1.3825x over previous
#include <cuda_runtime.h>
#include <cuda_fp16.h>
#include <cstdint>

#define NBATCH 4096
#define NTOK   64
#define NDIM   256
#define NHEADS 8
#define HD     32
#define NROWS  (NBATCH * NTOK)   // 262144

// ---------------- device scratch ---------------------------------------------
__device__ __align__(16) __half g_xf[(size_t)NROWS * 256];
__device__ __align__(16) __half g_of[(size_t)NROWS * 256];
__device__ __align__(16) __half g_wqf[768 * 256];
__device__ __align__(16) __half g_wpf[256 * 256];
__device__ __align__(16) __half g_qf[(size_t)NBATCH * NHEADS * NTOK * HD];
__device__ __align__(16) __half g_kf[(size_t)NBATCH * NHEADS * NTOK * HD];
__device__ __align__(16) __half g_vf[(size_t)NBATCH * NHEADS * NTOK * HD];
__device__ float g_bias[NHEADS * NTOK * NTOK];

// ---------------- helpers ----------------------------------------------------
__device__ __forceinline__ uint32_t s2u(const void* p) {
    return (uint32_t)__cvta_generic_to_shared(p);
}
#define LDM4(r0, r1, r2, r3, addr)                                              \
    asm volatile("ldmatrix.sync.aligned.m8n8.x4.shared.b16 {%0,%1,%2,%3}, [%4];"\
                 : "=r"(r0), "=r"(r1), "=r"(r2), "=r"(r3) : "r"(addr))
#define LDM4T(r0, r1, r2, r3, addr)                                             \
    asm volatile("ldmatrix.sync.aligned.m8n8.x4.trans.shared.b16 {%0,%1,%2,%3}, [%4];"\
                 : "=r"(r0), "=r"(r1), "=r"(r2), "=r"(r3) : "r"(addr))
#define CP16(dst, src)                                                          \
    asm volatile("cp.async.cg.shared.global [%0], [%1], 16;" :: "r"(dst), "l"(src))
#define CP_COMMIT() asm volatile("cp.async.commit_group;")
#define CP_WAIT0()  asm volatile("cp.async.wait_group 0;")
#define CP_WAIT1()  asm volatile("cp.async.wait_group 1;")

__device__ __forceinline__ void mma16h(float* c, const uint32_t* a, const uint32_t* b) {
    asm volatile(
        "mma.sync.aligned.m16n8k16.row.col.f32.f16.f16.f32 "
        "{%0,%1,%2,%3}, {%4,%5,%6,%7}, {%8,%9}, {%0,%1,%2,%3};"
        : "+f"(c[0]), "+f"(c[1]), "+f"(c[2]), "+f"(c[3])
        : "r"(a[0]), "r"(a[1]), "r"(a[2]), "r"(a[3]), "r"(b[0]), "r"(b[1]));
}

// ---------------------------------------------------------------------------
// One merged prep kernel.
// Block ranges: [0,65536) x | [65536,66304) wq | [66304,66560) wp | [66560,66688) bias
// ---------------------------------------------------------------------------
__global__ void prep_all(const float* __restrict__ x,
                         const float* __restrict__ wq, const float* __restrict__ wkv,
                         const float* __restrict__ pw,
                         const float* __restrict__ bias_table,
                         const int* __restrict__ rel_idx)
{
    const int bid = blockIdx.x;
    if (bid < 65536) {
        size_t i = (size_t)bid * 256 + threadIdx.x;
        float4 v = ((const float4*)x)[i];
        __half2 a = __floats2half2_rn(v.x, v.y);
        __half2 b = __floats2half2_rn(v.z, v.w);
        ((uint2*)g_xf)[i] = make_uint2(*(uint32_t*)&a, *(uint32_t*)&b);
    } else if (bid < 66304) {
        int idx = (bid - 65536) * 256 + threadIdx.x;   // [0, 196608)
        int c = idx >> 8, k = idx & 255;
        float v = (c < 256) ? wq[k * 256 + c] : wkv[k * 512 + (c - 256)];
        g_wqf[idx] = __float2half_rn(v);
    } else if (bid < 66560) {
        int idx = (bid - 66304) * 256 + threadIdx.x;   // [0, 65536)
        int c = idx >> 8, k = idx & 255;
        g_wpf[idx] = __float2half_rn(pw[k * 256 + c]);
    } else {
        int idx = (bid - 66560) * 256 + threadIdx.x;   // [0, 32768)
        int h = idx >> 12, rm = idx & 4095;
        g_bias[idx] = bias_table[rel_idx[rm] * NHEADS + h];
    }
}

// ---------------------------------------------------------------------------
// fp16 GEMM, cp.async 2-stage (R8-proven). C[128x128] = A[128x256] @ W^T.
// 256 thr / 8 warps (2m x 4n), warp tile 64x32, BK=32. smem 40KB.
// mode 0: qkv -> q/k/v single fp16 (q scaled). mode 1: proj -> fp32 out.
// ---------------------------------------------------------------------------
__global__ __launch_bounds__(256) void mm_fp16(
    const __half* __restrict__ A, const __half* __restrict__ W,
    const float* __restrict__ bq, const float* __restrict__ bkv,
    const float* __restrict__ pb, float* __restrict__ outp, int mode)
{
    extern __shared__ __align__(16) char sm[];
    const uint32_t sb = s2u(sm);
    const int t = threadIdx.x;
    const int lane = t & 31, wid = t >> 5;
    const int wm = wid & 1, wn = wid >> 1;
    const int gid = lane >> 2, t4 = lane & 3;
    const size_t row0 = (size_t)blockIdx.y * 128;
    const int col0 = blockIdx.x * 128;

    float c[4][4][4];
#pragma unroll
    for (int mt = 0; mt < 4; mt++)
#pragma unroll
        for (int nt = 0; nt < 4; nt++)
#pragma unroll
            for (int i = 0; i < 4; i++) c[mt][nt][i] = 0.f;

#define LOADG(S, BUF)                                                            \
    do {                                                                         \
        const int k0 = (S) * 32;                                                 \
        _Pragma("unroll")                                                        \
        for (int j = 0; j < 2; j++) {                                            \
            const int idx = j * 256 + t;                                         \
            const int r = idx >> 2, q = idx & 3;                                 \
            const uint32_t doff = (uint32_t)((BUF) * 10240 + r * 80 + q * 16);   \
            CP16(sb + doff,         A + (row0 + r) * 256 + k0 + q * 8);          \
            CP16(sb + 20480 + doff, W + (size_t)(col0 + r) * 256 + k0 + q * 8);  \
        }                                                                        \
        CP_COMMIT();                                                             \
    } while (0)

    LOADG(0, 0);

    const int arow = (lane & 7) + ((lane >> 3) & 1) * 8;
    const int aksh = ((lane >> 4) & 1) * 8;
    const int brow = (lane & 7) + ((lane >> 4) & 1) * 8;
    const int bksh = ((lane >> 3) & 1) * 8;

    for (int s = 0; s < 8; s++) {
        const int cur = s & 1;
        if (s < 7) { LOADG(s + 1, cur ^ 1); CP_WAIT1(); }
        else       { CP_WAIT0(); }
        __syncthreads();
#pragma unroll
        for (int kk = 0; kk < 2; kk++) {
            const int kb = kk * 16;
            uint32_t a[4][4];
#pragma unroll
            for (int mt = 0; mt < 4; mt++) {
                const int r = wm * 64 + mt * 16 + arow;
                const uint32_t aoff = (uint32_t)(cur * 10240 + r * 80 + (kb + aksh) * 2);
                LDM4(a[mt][0], a[mt][1], a[mt][2], a[mt][3], sb + aoff);
            }
#pragma unroll
            for (int ntp = 0; ntp < 2; ntp++) {
                const int nr = wn * 32 + ntp * 16 + brow;
                const uint32_t boff =
                    (uint32_t)(20480 + cur * 10240 + nr * 80 + (kb + bksh) * 2);
                uint32_t b[4];
                LDM4(b[0], b[1], b[2], b[3], sb + boff);
#pragma unroll
                for (int mt = 0; mt < 4; mt++) {
                    mma16h(c[mt][2 * ntp],     a[mt], b);
                    mma16h(c[mt][2 * ntp + 1], a[mt], b + 2);
                }
            }
        }
        __syncthreads();
    }

    // ---- epilogue ----
#pragma unroll
    for (int mt = 0; mt < 4; mt++) {
        const int rbase = wm * 64 + mt * 16 + gid;
#pragma unroll
        for (int h8 = 0; h8 < 2; h8++) {
            const size_t grow = row0 + rbase + h8 * 8;
#pragma unroll
            for (int nt = 0; nt < 4; nt++) {
                const int cib = wn * 32 + nt * 8 + t4 * 2;
                const float v0 = c[mt][nt][h8 * 2 + 0];
                const float v1 = c[mt][nt][h8 * 2 + 1];
                if (mode) {
                    const float2 pbv = *(const float2*)(pb + col0 + cib);
                    float2 o2; o2.x = v0 + pbv.x; o2.y = v1 + pbv.y;
                    *(float2*)(outp + grow * 256 + col0 + cib) = o2;
                } else {
                    const int region = col0 >> 8;          // 0=q 1=k 2=v
                    const int c2 = col0 - (region << 8) + cib;
                    const float* bias = (region == 0) ? bq
                                       : (region == 1) ? bkv : (bkv + 256);
                    const float2 bv = *(const float2*)(bias + c2);
                    const float scl = (region == 0) ? 0.17677669529663687f : 1.0f;
                    __half* dst = (region == 0) ? g_qf : (region == 1) ? g_kf : g_vf;
                    const int win = (int)(grow >> 6), nn = (int)(grow & 63);
                    const int hh = c2 >> 5, d = c2 & 31;
                    const size_t di = (((size_t)win * NHEADS + hh) * NTOK + nn) * HD + d;
                    __half2 p = __floats2half2_rn((v0 + bv.x) * scl,
                                                  (v1 + bv.y) * scl);
                    *(uint32_t*)(dst + di) = *(uint32_t*)&p;
                }
            }
        }
    }
#undef LOADG
}

// ---------------------------------------------------------------------------
// Attention, all-single fp16. Block = one (b,h), 128 thr / 4 warps.
// smem bytes: Q 0, K 5120, V 10240  (each [64][40] fp16, 80B rows);
//             S 15360 + wid*2304   ([16][72] fp16, 144B rows). total 24576
// ---------------------------------------------------------------------------
__global__ __launch_bounds__(128) void attn_f16(const float* __restrict__ w)
{
    extern __shared__ __align__(16) char sm[];
    const uint32_t sb = s2u(sm);
    const int bh = blockIdx.x, h = bh & 7;
    const int t = threadIdx.x, lane = t & 31, wid = t >> 5;
    const int gid = lane >> 2, t4 = lane & 3;

    {
        const size_t gbase = (size_t)bh * 2048;
#pragma unroll
        for (int j = 0; j < 2; j++) {
            const int idx = j * 128 + t;
            const int r = idx >> 2, q = idx & 3;
            const uint32_t doff = (uint32_t)(r * 80 + q * 16);
            const size_t soff = gbase + r * 32 + q * 8;
            CP16(sb + doff,         g_qf + soff);
            CP16(sb + 5120 + doff,  g_kf + soff);
            CP16(sb + 10240 + doff, g_vf + soff);
        }
        CP_COMMIT();
    }
    CP_WAIT0();
    __syncthreads();

    const int arow = (lane & 7) + ((lane >> 3) & 1) * 8;
    const int aksh = ((lane >> 4) & 1) * 8;
    const int brow = (lane & 7) + ((lane >> 4) & 1) * 8;
    const int bksh = ((lane >> 3) & 1) * 8;
    const int vrow = (lane & 7) + ((lane >> 3) & 1) * 8;
    const int vcsh = ((lane >> 4) & 1) * 8;

    // ---- S = Q@K^T (single-term) ----
    float c[8][4];
#pragma unroll
    for (int nt = 0; nt < 8; nt++)
#pragma unroll
        for (int i = 0; i < 4; i++) c[nt][i] = 0.f;

#pragma unroll
    for (int kk = 0; kk < 2; kk++) {
        const int kb16 = kk * 16;
        uint32_t a[4];
        const uint32_t qoff = (uint32_t)((wid * 16 + arow) * 80 + (kb16 + aksh) * 2);
        LDM4(a[0], a[1], a[2], a[3], sb + qoff);
#pragma unroll
        for (int ntp = 0; ntp < 4; ntp++) {
            const uint32_t koff =
                (uint32_t)(5120 + (ntp * 16 + brow) * 80 + (kb16 + bksh) * 2);
            uint32_t bk[4];
            LDM4(bk[0], bk[1], bk[2], bk[3], sb + koff);
            mma16h(c[2 * ntp],     a, bk);
            mma16h(c[2 * ntp + 1], a, bk + 2);
        }
    }

    // ---- bias add ----
    const int r0 = wid * 16 + gid;
    const float* b0p = g_bias + ((size_t)h * 64 + r0) * 64;
    const float* b1p = b0p + 8 * 64;
#pragma unroll
    for (int nt = 0; nt < 8; nt++) {
        const int cc = nt * 8 + 2 * t4;
        const float2 x0 = *(const float2*)(b0p + cc);
        const float2 x1 = *(const float2*)(b1p + cc);
        c[nt][0] += x0.x; c[nt][1] += x0.y;
        c[nt][2] += x1.x; c[nt][3] += x1.y;
    }

    // ---- softmax sums ----
    float p0 = 0.f, p1 = 0.f;
#pragma unroll
    for (int nt = 0; nt < 8; nt++) {
        p0 += __expf(c[nt][0]) + __expf(c[nt][1]);
        p1 += __expf(c[nt][2]) + __expf(c[nt][3]);
    }
    p0 += __shfl_xor_sync(0xFFFFFFFF, p0, 1);
    p0 += __shfl_xor_sync(0xFFFFFFFF, p0, 2);
    p1 += __shfl_xor_sync(0xFFFFFFFF, p1, 1);
    p1 += __shfl_xor_sync(0xFFFFFFFF, p1, 2);

    const float w0 = w[0], w1 = w[1];
    const float wmx = fmaxf(w0, w1);
    const float e0 = __expf(w0 - wmx), e1 = __expf(w1 - wmx);
    const float winv = 1.f / (e0 + e1);
    const float ww0 = e0 * winv, ww1 = e1 * winv;
    const float k00 = ww0 / p0, k01 = ww0 / p1;

    // ---- combined weights -> S single fp16 smem ----
    const uint32_t sh0 = 15360 + wid * 2304;
#pragma unroll
    for (int nt = 0; nt < 8; nt++) {
        const int cc = nt * 8 + 2 * t4;
        const float q00 = fmaxf(c[nt][0], 0.f), q01 = fmaxf(c[nt][1], 0.f);
        const float q10 = fmaxf(c[nt][2], 0.f), q11 = fmaxf(c[nt][3], 0.f);
        const float a0 = __expf(c[nt][0]) * k00 + q00 * q00 * ww1;
        const float a1 = __expf(c[nt][1]) * k00 + q01 * q01 * ww1;
        const float a2 = __expf(c[nt][2]) * k01 + q10 * q10 * ww1;
        const float a3 = __expf(c[nt][3]) * k01 + q11 * q11 * ww1;
        __half2 h01 = __floats2half2_rn(a0, a1);
        __half2 h23 = __floats2half2_rn(a2, a3);
        *(uint32_t*)(sm + sh0 + gid * 144 + cc * 2) = *(uint32_t*)&h01;
        *(uint32_t*)(sm + sh0 + (gid + 8) * 144 + cc * 2) = *(uint32_t*)&h23;
    }
    __syncwarp();

    // ---- O = A @ V (single-term), V via ldmatrix.trans ----
    float o[4][4];
#pragma unroll
    for (int nt = 0; nt < 4; nt++)
#pragma unroll
        for (int i = 0; i < 4; i++) o[nt][i] = 0.f;

#pragma unroll
    for (int kc = 0; kc < 4; kc++) {
        const int kb16 = kc * 16;
        uint32_t a[4];
        const uint32_t soff = (uint32_t)(arow * 144 + (kb16 + aksh) * 2);
        LDM4(a[0], a[1], a[2], a[3], sb + sh0 + soff);
#pragma unroll
        for (int ntp = 0; ntp < 2; ntp++) {
            const uint32_t voff =
                (uint32_t)(10240 + (kb16 + vrow) * 80 + (ntp * 16 + vcsh) * 2);
            uint32_t bv[4];
            LDM4T(bv[0], bv[1], bv[2], bv[3], sb + voff);
            mma16h(o[2 * ntp],     a, bv);
            mma16h(o[2 * ntp + 1], a, bv + 2);
        }
    }

    // ---- write O fp16 ----
    const size_t obase = ((size_t)(bh >> 3) * 64) * 256 + h * 32;
#pragma unroll
    for (int nt = 0; nt < 4; nt++) {
        const int d = nt * 8 + 2 * t4;
        __half2 v0 = __floats2half2_rn(o[nt][0], o[nt][1]);
        __half2 v1 = __floats2half2_rn(o[nt][2], o[nt][3]);
        *(uint32_t*)(g_of + obase + (size_t)r0 * 256 + d) = *(uint32_t*)&v0;
        *(uint32_t*)(g_of + obase + (size_t)(r0 + 8) * 256 + d) = *(uint32_t*)&v1;
    }
}

// ---------------------------------------------------------------------------
extern "C" void kernel_launch(void* const* d_in, const int* in_sizes, int n_in,
                              void* d_out, int out_size)
{
    const float* x   = (const float*)d_in[0];
    const float* wq  = (const float*)d_in[1];
    const float* bq  = (const float*)d_in[2];
    const float* wkv = (const float*)d_in[3];
    const float* bkv = (const float*)d_in[4];
    const float* bt  = (const float*)d_in[5];
    const float* w   = (const float*)d_in[6];
    const float* pw  = (const float*)d_in[7];
    const float* pb  = (const float*)d_in[8];
    const int*   ri  = (const int*)d_in[9];
    float* out = (float*)d_out;

    __half *xf, *of, *wqf, *wpf;
    cudaGetSymbolAddress((void**)&xf,  g_xf);
    cudaGetSymbolAddress((void**)&of,  g_of);
    cudaGetSymbolAddress((void**)&wqf, g_wqf);
    cudaGetSymbolAddress((void**)&wpf, g_wpf);

    prep_all<<<66688, 256>>>(x, wq, wkv, pw, bt, ri);
    mm_fp16<<<dim3(6, NROWS / 128), 256, 40960>>>(xf, wqf, bq, bkv,
                                                  nullptr, nullptr, 0);
    attn_f16<<<NBATCH * NHEADS, 128, 24576>>>(w);
    mm_fp16<<<dim3(2, NROWS / 128), 256, 40960>>>(of, wpf, nullptr, nullptr,
                                                  pb, out, 1);
}